// round 15
// baseline (speedup 1.0000x reference)
#include <cuda_runtime.h>
#include <cstdint>

#define BB 4
#define CC 256
#define HH 56
#define WW 56
#define CR 64          // C / 4
#define GG 16          // groups
#define GC 16
#define KK 7
#define K2T 49
#define M2 784         // GG * K2T
#define HW 3136        // HH * WW
#define PAD 3
#define NBAND 28       // 2-row bands
#define BPX 112        // px per band
#define WTILE (K2T * BPX)   // 5488 floats per (b,g,band)

// Scratch (__device__ globals; no allocations allowed)
__device__ float g_w1[BB * CR * HW];                 // [b][Cr][HW]
__device__ float g_w2t[BB * GG * NBAND * WTILE];     // [b][g][band][tap][px]

// ---------------------------------------------------------------------------
// K1: w1 = relu(bn(conv1_1x1(x))). Tile 64o x 32px, 128 thr, 4x4, k-step 64.
// (round-5 version, measured 21.0 us — best K1 so far)
// ---------------------------------------------------------------------------
__global__ __launch_bounds__(128) void k1_conv1_bn_relu(
        const float* __restrict__ x,
        const float* __restrict__ w1w,
        const float* __restrict__ gamma,
        const float* __restrict__ beta,
        const float* __restrict__ mean,
        const float* __restrict__ var) {
    __shared__ float As[64 * 68];    // [k][o]
    __shared__ float Bs[64 * 32];    // [k][px]

    const int tid = threadIdx.x;
    const int tx = tid & 7;
    const int ty = tid >> 3;
    const int px0 = blockIdx.x * 32;
    const int b = blockIdx.y;

    float acc[4][4];
#pragma unroll
    for (int i = 0; i < 4; ++i)
#pragma unroll
        for (int u = 0; u < 4; ++u) acc[i][u] = 0.f;

    for (int kt = 0; kt < CC; kt += 64) {
        {
            int k = tid & 63;
            int oh = tid >> 6;
#pragma unroll
            for (int r = 0; r < 32; ++r) {
                int o = 2 * r + oh;
                As[k * 68 + o] = w1w[o * CC + kt + k];
            }
        }
        {
            int j = tid & 31;
            int kh = tid >> 5;
#pragma unroll
            for (int r = 0; r < 16; ++r) {
                int k = 4 * r + kh;
                Bs[k * 32 + j] = x[(size_t)(b * CC + kt + k) * HW + px0 + j];
            }
        }
        __syncthreads();

#pragma unroll 16
        for (int k = 0; k < 64; ++k) {
            float4 av = *(const float4*)&As[k * 68 + ty * 4];
            float4 bv = *(const float4*)&Bs[k * 32 + tx * 4];
            acc[0][0] = fmaf(av.x, bv.x, acc[0][0]);
            acc[0][1] = fmaf(av.x, bv.y, acc[0][1]);
            acc[0][2] = fmaf(av.x, bv.z, acc[0][2]);
            acc[0][3] = fmaf(av.x, bv.w, acc[0][3]);
            acc[1][0] = fmaf(av.y, bv.x, acc[1][0]);
            acc[1][1] = fmaf(av.y, bv.y, acc[1][1]);
            acc[1][2] = fmaf(av.y, bv.z, acc[1][2]);
            acc[1][3] = fmaf(av.y, bv.w, acc[1][3]);
            acc[2][0] = fmaf(av.z, bv.x, acc[2][0]);
            acc[2][1] = fmaf(av.z, bv.y, acc[2][1]);
            acc[2][2] = fmaf(av.z, bv.z, acc[2][2]);
            acc[2][3] = fmaf(av.z, bv.w, acc[2][3]);
            acc[3][0] = fmaf(av.w, bv.x, acc[3][0]);
            acc[3][1] = fmaf(av.w, bv.y, acc[3][1]);
            acc[3][2] = fmaf(av.w, bv.z, acc[3][2]);
            acc[3][3] = fmaf(av.w, bv.w, acc[3][3]);
        }
        __syncthreads();
    }

#pragma unroll
    for (int i = 0; i < 4; ++i) {
        int o = ty * 4 + i;
        float sc = gamma[o] * rsqrtf(var[o] + 1e-5f);
        float sh = beta[o] - mean[o] * sc;
        float4 v;
        v.x = fmaxf(fmaf(acc[i][0], sc, sh), 0.f);
        v.y = fmaxf(fmaf(acc[i][1], sc, sh), 0.f);
        v.z = fmaxf(fmaf(acc[i][2], sc, sh), 0.f);
        v.w = fmaxf(fmaf(acc[i][3], sc, sh), 0.f);
        *(float4*)(g_w1 + (size_t)(b * CR + o) * HW + px0 + tx * 4) = v;
    }
}

// ---------------------------------------------------------------------------
// K2: w2t = conv2_1x1(w1) + bias, written in K3-friendly tiled layout
// [b][g][band][tap][112]. Tile 64o x 112px (one band), 224 thr, 8o x 4px.
// ---------------------------------------------------------------------------
__global__ __launch_bounds__(224) void k2_conv2(
        const float* __restrict__ w2w,
        const float* __restrict__ w2b) {
    __shared__ float As[64 * 68];     // [k][o]
    __shared__ float Bs[64 * BPX];    // [k][px]

    const int tid = threadIdx.x;
    const int tx = tid % 28;          // px quad (28 quads = 112 px)
    const int ty = tid / 28;          // o octet (8 octets = 64 o)
    const int band = blockIdx.x;      // 28 bands
    const int o0 = blockIdx.y * 64;   // 13 tiles, guard at 784
    const int b = blockIdx.z;
    const int px0 = band * BPX;       // global hw offset

    // As: [k][o] transposed
    for (int idx = tid; idx < 64 * 64; idx += 224) {
        int o = idx >> 6, k = idx & 63;
        As[k * 68 + o] = (o0 + o < M2) ? w2w[(o0 + o) * CR + k] : 0.f;
    }
    // Bs: [k][px], 7168 = 32 exact iterations
    for (int idx = tid; idx < 64 * BPX; idx += 224) {
        int k = idx / BPX, p = idx - (idx / BPX) * BPX;
        Bs[k * BPX + p] = g_w1[(size_t)(b * CR + k) * HW + px0 + p];
    }
    __syncthreads();

    float acc[8][4];
#pragma unroll
    for (int i = 0; i < 8; ++i)
#pragma unroll
        for (int u = 0; u < 4; ++u) acc[i][u] = 0.f;

#pragma unroll 8
    for (int k = 0; k < 64; ++k) {
        float4 a0 = *(const float4*)&As[k * 68 + ty * 8];
        float4 a1 = *(const float4*)&As[k * 68 + ty * 8 + 4];
        float4 bv = *(const float4*)&Bs[k * BPX + tx * 4];
        float av[8] = {a0.x, a0.y, a0.z, a0.w, a1.x, a1.y, a1.z, a1.w};
#pragma unroll
        for (int i = 0; i < 8; ++i) {
            acc[i][0] = fmaf(av[i], bv.x, acc[i][0]);
            acc[i][1] = fmaf(av[i], bv.y, acc[i][1]);
            acc[i][2] = fmaf(av[i], bv.z, acc[i][2]);
            acc[i][3] = fmaf(av[i], bv.w, acc[i][3]);
        }
    }

#pragma unroll
    for (int i = 0; i < 8; ++i) {
        int o = o0 + ty * 8 + i;
        if (o >= M2) continue;
        int g = o / K2T;
        int tap = o - g * K2T;
        float bias = w2b[o];
        float4 v;
        v.x = acc[i][0] + bias;
        v.y = acc[i][1] + bias;
        v.z = acc[i][2] + bias;
        v.w = acc[i][3] + bias;
        *(float4*)(g_w2t + ((size_t)((b * GG + g) * NBAND + band)) * WTILE
                   + tap * BPX + tx * 4) = v;
    }
}

// ---------------------------------------------------------------------------
// K3: involution reduce. Block = (2-row band, group, batch); 224 threads.
// Thread = 4 px x 2 ch. Weights read from the CONTIGUOUS 21.4KB per-block
// tile in g_w2t (sequential DRAM/L2 streams instead of 12.5KB-strided).
// ---------------------------------------------------------------------------
__global__ __launch_bounds__(224) void k3_involution(
        const float* __restrict__ x,
        float* __restrict__ out) {
    __shared__ float xs[8 * 16 * 64];   // [row][ch][64(+3 shift)] 32KB

    const int tid = threadIdx.x;
    const int band = blockIdx.x;
    const int g = blockIdx.y;
    const int b = blockIdx.z;
    const int h0 = band * 2;

    // stage x: rows h0-3 .. h0+4, cols -3..60 (clipped)
    const float* xg = x + (size_t)(b * CC + g * GC) * HW;
    for (int i = tid; i < 8 * 16 * 64; i += 224) {
        int row = i >> 10;
        int ch = (i >> 6) & 15;
        int col = i & 63;
        int hh = h0 - 3 + row;
        int ww = col - 3;
        float v = 0.f;
        if (hh >= 0 && hh < HH && (unsigned)ww < (unsigned)WW)
            v = xg[(size_t)ch * HW + hh * WW + ww];
        xs[i] = v;
    }
    __syncthreads();

    // mapping: q (14 px quads), cg (8 ch pairs), r (2 rows)
    const int q = tid % 14;
    const int cg = (tid / 14) & 7;
    const int r = tid / 112;
    const int w0 = q * 4;
    const int h = h0 + r;

    const float* wt = g_w2t + ((size_t)((b * GG + g) * NBAND + band)) * WTILE
                    + r * 56 + w0;

    float acc[2][4];
#pragma unroll
    for (int c = 0; c < 2; ++c)
#pragma unroll
        for (int p = 0; p < 4; ++p) acc[c][p] = 0.f;

#pragma unroll
    for (int ki = 0; ki < KK; ++ki) {
        float4 wv[7];
#pragma unroll
        for (int kj = 0; kj < KK; ++kj)
            wv[kj] = *(const float4*)(wt + (ki * KK + kj) * BPX);
#pragma unroll
        for (int c = 0; c < 2; ++c) {
            const float* xr = &xs[(r + ki) * 1024 + (cg * 2 + c) * 64 + w0];
            float4 xa = *(const float4*)(xr);
            float4 xb = *(const float4*)(xr + 4);
            float4 xc = *(const float4*)(xr + 8);
            float xw[12] = {xa.x, xa.y, xa.z, xa.w,
                            xb.x, xb.y, xb.z, xb.w,
                            xc.x, xc.y, xc.z, xc.w};
#pragma unroll
            for (int kj = 0; kj < KK; ++kj) {
                acc[c][0] = fmaf(wv[kj].x, xw[kj + 0], acc[c][0]);
                acc[c][1] = fmaf(wv[kj].y, xw[kj + 1], acc[c][1]);
                acc[c][2] = fmaf(wv[kj].z, xw[kj + 2], acc[c][2]);
                acc[c][3] = fmaf(wv[kj].w, xw[kj + 3], acc[c][3]);
            }
        }
    }

#pragma unroll
    for (int c = 0; c < 2; ++c) {
        float4 v = make_float4(acc[c][0], acc[c][1], acc[c][2], acc[c][3]);
        *(float4*)(out + (size_t)(b * CC + g * GC + cg * 2 + c) * HW
                   + h * WW + w0) = v;
    }
}

// ---------------------------------------------------------------------------
extern "C" void kernel_launch(void* const* d_in, const int* in_sizes, int n_in,
                              void* d_out, int out_size) {
    const float* x     = (const float*)d_in[0];
    const float* w1w   = (const float*)d_in[1];
    const float* gamma = (const float*)d_in[2];
    const float* beta  = (const float*)d_in[3];
    const float* mean  = (const float*)d_in[4];
    const float* var   = (const float*)d_in[5];
    const float* w2w   = (const float*)d_in[6];
    const float* w2b   = (const float*)d_in[7];
    float* out = (float*)d_out;

    dim3 g1(HW / 32, BB);                       // 98 x 4
    k1_conv1_bn_relu<<<g1, 128>>>(x, w1w, gamma, beta, mean, var);

    dim3 g2(NBAND, (M2 + 63) / 64, BB);         // 28 x 13 x 4 = 1456
    k2_conv2<<<g2, 224>>>(w2w, w2b);

    dim3 g3(NBAND, GG, BB);                     // 28 x 16 x 4 = 1792
    k3_involution<<<g3, 224>>>(x, out);
}

// round 16
// speedup vs baseline: 1.2030x; 1.2030x over previous
#include <cuda_runtime.h>
#include <cstdint>

#define BB 4
#define CC 256
#define HH 56
#define WW 56
#define CR 64          // C / 4
#define GG 16          // groups
#define GC 16
#define KK 7
#define K2T 49
#define M2 784         // GG * K2T
#define HW 3136        // HH * WW
#define PAD 3

// Scratch (__device__ globals; no allocations allowed)
__device__ float g_w1[BB * CR * HW];        // [B, Cr, HW]
__device__ float g_w2[BB * M2 * HW];        // [B, G*49, HW]

// ---------------------------------------------------------------------------
// K1: w1 = relu(bn(conv1_1x1(x))).  GEMM [64 x 256] x [256 x 3136] per batch.
// Tile 64o x 32px, 128 threads, 4x4 per thread, k-step 64. (round-5, 20.4us)
// ---------------------------------------------------------------------------
__global__ __launch_bounds__(128) void k1_conv1_bn_relu(
        const float* __restrict__ x,
        const float* __restrict__ w1w,
        const float* __restrict__ gamma,
        const float* __restrict__ beta,
        const float* __restrict__ mean,
        const float* __restrict__ var) {
    __shared__ float As[64 * 68];    // [k][o]
    __shared__ float Bs[64 * 32];    // [k][px]

    const int tid = threadIdx.x;
    const int tx = tid & 7;
    const int ty = tid >> 3;
    const int px0 = blockIdx.x * 32;
    const int b = blockIdx.y;

    float acc[4][4];
#pragma unroll
    for (int i = 0; i < 4; ++i)
#pragma unroll
        for (int u = 0; u < 4; ++u) acc[i][u] = 0.f;

    for (int kt = 0; kt < CC; kt += 64) {
        {
            int k = tid & 63;
            int oh = tid >> 6;
#pragma unroll
            for (int r = 0; r < 32; ++r) {
                int o = 2 * r + oh;
                As[k * 68 + o] = w1w[o * CC + kt + k];
            }
        }
        {
            int j = tid & 31;
            int kh = tid >> 5;
#pragma unroll
            for (int r = 0; r < 16; ++r) {
                int k = 4 * r + kh;
                Bs[k * 32 + j] = x[(size_t)(b * CC + kt + k) * HW + px0 + j];
            }
        }
        __syncthreads();

#pragma unroll 16
        for (int k = 0; k < 64; ++k) {
            float4 av = *(const float4*)&As[k * 68 + ty * 4];
            float4 bv = *(const float4*)&Bs[k * 32 + tx * 4];
            acc[0][0] = fmaf(av.x, bv.x, acc[0][0]);
            acc[0][1] = fmaf(av.x, bv.y, acc[0][1]);
            acc[0][2] = fmaf(av.x, bv.z, acc[0][2]);
            acc[0][3] = fmaf(av.x, bv.w, acc[0][3]);
            acc[1][0] = fmaf(av.y, bv.x, acc[1][0]);
            acc[1][1] = fmaf(av.y, bv.y, acc[1][1]);
            acc[1][2] = fmaf(av.y, bv.z, acc[1][2]);
            acc[1][3] = fmaf(av.y, bv.w, acc[1][3]);
            acc[2][0] = fmaf(av.z, bv.x, acc[2][0]);
            acc[2][1] = fmaf(av.z, bv.y, acc[2][1]);
            acc[2][2] = fmaf(av.z, bv.z, acc[2][2]);
            acc[2][3] = fmaf(av.z, bv.w, acc[2][3]);
            acc[3][0] = fmaf(av.w, bv.x, acc[3][0]);
            acc[3][1] = fmaf(av.w, bv.y, acc[3][1]);
            acc[3][2] = fmaf(av.w, bv.z, acc[3][2]);
            acc[3][3] = fmaf(av.w, bv.w, acc[3][3]);
        }
        __syncthreads();
    }

#pragma unroll
    for (int i = 0; i < 4; ++i) {
        int o = ty * 4 + i;
        float sc = gamma[o] * rsqrtf(var[o] + 1e-5f);
        float sh = beta[o] - mean[o] * sc;
        float4 v;
        v.x = fmaxf(fmaf(acc[i][0], sc, sh), 0.f);
        v.y = fmaxf(fmaf(acc[i][1], sc, sh), 0.f);
        v.z = fmaxf(fmaf(acc[i][2], sc, sh), 0.f);
        v.w = fmaxf(fmaf(acc[i][3], sc, sh), 0.f);
        *(float4*)(g_w1 + (size_t)(b * CR + o) * HW + px0 + tx * 4) = v;
    }
}

// ---------------------------------------------------------------------------
// K2: w2 = conv2_1x1(w1) + bias. Tile 64o x 64px, 128 thr, 8x4. (round-8)
// ---------------------------------------------------------------------------
__global__ __launch_bounds__(128) void k2_conv2(
        const float* __restrict__ w2w,
        const float* __restrict__ w2b) {
    __shared__ float As[64 * 68];
    __shared__ float Bs[64 * 64];

    const int tid = threadIdx.x;
    const int tx = tid & 15;
    const int ty = tid >> 4;
    const int px0 = blockIdx.x * 64;
    const int o0 = blockIdx.y * 64;
    const int b = blockIdx.z;

    {
        int k = tid & 63;
        int oh = tid >> 6;
#pragma unroll
        for (int r = 0; r < 32; ++r) {
            int o = 2 * r + oh;
            As[k * 68 + o] = (o0 + o < M2) ? w2w[(o0 + o) * CR + k] : 0.f;
        }
    }
    {
        int j = tid & 63;
        int kh = tid >> 6;
#pragma unroll
        for (int r = 0; r < 32; ++r) {
            int k = 2 * r + kh;
            Bs[k * 64 + j] = g_w1[(size_t)(b * CR + k) * HW + px0 + j];
        }
    }
    __syncthreads();

    float acc[8][4];
#pragma unroll
    for (int i = 0; i < 8; ++i)
#pragma unroll
        for (int u = 0; u < 4; ++u) acc[i][u] = 0.f;

#pragma unroll 8
    for (int k = 0; k < 64; ++k) {
        float4 a0 = *(const float4*)&As[k * 68 + ty * 8];
        float4 a1 = *(const float4*)&As[k * 68 + ty * 8 + 4];
        float4 bv = *(const float4*)&Bs[k * 64 + tx * 4];
        float av[8] = {a0.x, a0.y, a0.z, a0.w, a1.x, a1.y, a1.z, a1.w};
#pragma unroll
        for (int i = 0; i < 8; ++i) {
            acc[i][0] = fmaf(av[i], bv.x, acc[i][0]);
            acc[i][1] = fmaf(av[i], bv.y, acc[i][1]);
            acc[i][2] = fmaf(av[i], bv.z, acc[i][2]);
            acc[i][3] = fmaf(av[i], bv.w, acc[i][3]);
        }
    }

#pragma unroll
    for (int i = 0; i < 8; ++i) {
        int o = o0 + ty * 8 + i;
        if (o >= M2) continue;
        float bias = w2b[o];
        float4 v;
        v.x = acc[i][0] + bias;
        v.y = acc[i][1] + bias;
        v.z = acc[i][2] + bias;
        v.w = acc[i][3] + bias;
        *(float4*)(g_w2 + (size_t)(b * M2 + o) * HW + px0 + tx * 4) = v;
    }
}

// ---------------------------------------------------------------------------
// K3: involution reduce. Block = (4-row band, group, batch); 224 threads.
// Thread = 4 px x 4 ch, register double-buffered weight prefetch. (round-9)
// ---------------------------------------------------------------------------
__global__ __launch_bounds__(224, 3) void k3_involution(
        const float* __restrict__ x,
        float* __restrict__ out) {
    __shared__ float xs[GC * 10 * 64];

    const int tid = threadIdx.x;
    const int h0 = blockIdx.x * 4;
    const int g = blockIdx.y;
    const int b = blockIdx.z;

    const float* xg = x + (size_t)(b * CC + g * GC) * HW;
    for (int i = tid; i < GC * 10 * 64; i += 224) {
        int ch = i / 640;
        int rem = i - ch * 640;
        int rr = rem >> 6;
        int c = rem & 63;
        int hh = h0 - 3 + rr;
        int ww = c - 3;
        float v = 0.f;
        if (hh >= 0 && hh < HH && ww >= 0 && ww < WW)
            v = xg[(size_t)ch * HW + hh * WW + ww];
        xs[i] = v;
    }
    __syncthreads();

    const int q = tid % 14;
    const int cg = (tid / 14) & 3;
    const int r = tid / 56;
    const int w0 = q * 4;
    const int h = h0 + r;

    const float* wg = g_w2 + ((size_t)(b * GG + g) * K2T) * HW + h * WW + w0;

    float acc[4][4];
#pragma unroll
    for (int c = 0; c < 4; ++c)
#pragma unroll
        for (int p = 0; p < 4; ++p) acc[c][p] = 0.f;

    // prime: taps of ki = 0
    float4 wcur[7], wnxt[7];
#pragma unroll
    for (int kj = 0; kj < KK; ++kj)
        wcur[kj] = *(const float4*)(wg + (size_t)kj * HW);

#pragma unroll
    for (int ki = 0; ki < KK; ++ki) {
        if (ki < KK - 1) {
#pragma unroll
            for (int kj = 0; kj < KK; ++kj)
                wnxt[kj] = *(const float4*)(wg + (size_t)((ki + 1) * KK + kj) * HW);
        }
#pragma unroll
        for (int c = 0; c < 4; ++c) {
            const float* xr = &xs[(cg * 4 + c) * 640 + (r + ki) * 64 + w0];
            float4 xa = *(const float4*)(xr);
            float4 xb = *(const float4*)(xr + 4);
            float4 xc = *(const float4*)(xr + 8);
            float xw[12] = {xa.x, xa.y, xa.z, xa.w,
                            xb.x, xb.y, xb.z, xb.w,
                            xc.x, xc.y, xc.z, xc.w};
#pragma unroll
            for (int kj = 0; kj < KK; ++kj) {
                acc[c][0] = fmaf(wcur[kj].x, xw[kj + 0], acc[c][0]);
                acc[c][1] = fmaf(wcur[kj].y, xw[kj + 1], acc[c][1]);
                acc[c][2] = fmaf(wcur[kj].z, xw[kj + 2], acc[c][2]);
                acc[c][3] = fmaf(wcur[kj].w, xw[kj + 3], acc[c][3]);
            }
        }
#pragma unroll
        for (int kj = 0; kj < KK; ++kj)
            wcur[kj] = wnxt[kj];
    }

#pragma unroll
    for (int c = 0; c < 4; ++c) {
        float4 v = make_float4(acc[c][0], acc[c][1], acc[c][2], acc[c][3]);
        *(float4*)(out + (size_t)(b * CC + g * GC + cg * 4 + c) * HW
                   + h * WW + w0) = v;
    }
}

// ---------------------------------------------------------------------------
extern "C" void kernel_launch(void* const* d_in, const int* in_sizes, int n_in,
                              void* d_out, int out_size) {
    const float* x     = (const float*)d_in[0];
    const float* w1w   = (const float*)d_in[1];
    const float* gamma = (const float*)d_in[2];
    const float* beta  = (const float*)d_in[3];
    const float* mean  = (const float*)d_in[4];
    const float* var   = (const float*)d_in[5];
    const float* w2w   = (const float*)d_in[6];
    const float* w2b   = (const float*)d_in[7];
    float* out = (float*)d_out;

    dim3 g1(HW / 32, BB);                       // 98 x 4 = 392
    k1_conv1_bn_relu<<<g1, 128>>>(x, w1w, gamma, beta, mean, var);

    dim3 g2(HW / 64, (M2 + 63) / 64, BB);       // 49 x 13 x 4 = 2548
    k2_conv2<<<g2, 128>>>(w2w, w2b);

    dim3 g3(HH / 4, GG, BB);                    // 14 x 16 x 4 = 896
    k3_involution<<<g3, 224>>>(x, out);
}

// round 17
// speedup vs baseline: 1.2578x; 1.0456x over previous
#include <cuda_runtime.h>
#include <cuda_fp16.h>
#include <cstdint>

#define BB 4
#define CC 256
#define HH 56
#define WW 56
#define CR 64          // C / 4
#define GG 16          // groups
#define GC 16
#define KK 7
#define K2T 49
#define M2 784         // GG * K2T
#define HW 3136        // HH * WW
#define PAD 3

// Scratch (__device__ globals; no allocations allowed)
__device__ float g_w1[BB * CR * HW];         // [B, Cr, HW] fp32
__device__ __half g_w2h[BB * M2 * HW];       // [B, G*49, HW] fp16 (19.6MB)

// ---------------------------------------------------------------------------
// K1: w1 = relu(bn(conv1_1x1(x))).  GEMM [64 x 256] x [256 x 3136] per batch.
// Tile 64o x 32px, 128 threads, 4x4 per thread, k-step 64. (round-5, 20.4us)
// ---------------------------------------------------------------------------
__global__ __launch_bounds__(128) void k1_conv1_bn_relu(
        const float* __restrict__ x,
        const float* __restrict__ w1w,
        const float* __restrict__ gamma,
        const float* __restrict__ beta,
        const float* __restrict__ mean,
        const float* __restrict__ var) {
    __shared__ float As[64 * 68];    // [k][o]
    __shared__ float Bs[64 * 32];    // [k][px]

    const int tid = threadIdx.x;
    const int tx = tid & 7;
    const int ty = tid >> 3;
    const int px0 = blockIdx.x * 32;
    const int b = blockIdx.y;

    float acc[4][4];
#pragma unroll
    for (int i = 0; i < 4; ++i)
#pragma unroll
        for (int u = 0; u < 4; ++u) acc[i][u] = 0.f;

    for (int kt = 0; kt < CC; kt += 64) {
        {
            int k = tid & 63;
            int oh = tid >> 6;
#pragma unroll
            for (int r = 0; r < 32; ++r) {
                int o = 2 * r + oh;
                As[k * 68 + o] = w1w[o * CC + kt + k];
            }
        }
        {
            int j = tid & 31;
            int kh = tid >> 5;
#pragma unroll
            for (int r = 0; r < 16; ++r) {
                int k = 4 * r + kh;
                Bs[k * 32 + j] = x[(size_t)(b * CC + kt + k) * HW + px0 + j];
            }
        }
        __syncthreads();

#pragma unroll 16
        for (int k = 0; k < 64; ++k) {
            float4 av = *(const float4*)&As[k * 68 + ty * 4];
            float4 bv = *(const float4*)&Bs[k * 32 + tx * 4];
            acc[0][0] = fmaf(av.x, bv.x, acc[0][0]);
            acc[0][1] = fmaf(av.x, bv.y, acc[0][1]);
            acc[0][2] = fmaf(av.x, bv.z, acc[0][2]);
            acc[0][3] = fmaf(av.x, bv.w, acc[0][3]);
            acc[1][0] = fmaf(av.y, bv.x, acc[1][0]);
            acc[1][1] = fmaf(av.y, bv.y, acc[1][1]);
            acc[1][2] = fmaf(av.y, bv.z, acc[1][2]);
            acc[1][3] = fmaf(av.y, bv.w, acc[1][3]);
            acc[2][0] = fmaf(av.z, bv.x, acc[2][0]);
            acc[2][1] = fmaf(av.z, bv.y, acc[2][1]);
            acc[2][2] = fmaf(av.z, bv.z, acc[2][2]);
            acc[2][3] = fmaf(av.z, bv.w, acc[2][3]);
            acc[3][0] = fmaf(av.w, bv.x, acc[3][0]);
            acc[3][1] = fmaf(av.w, bv.y, acc[3][1]);
            acc[3][2] = fmaf(av.w, bv.z, acc[3][2]);
            acc[3][3] = fmaf(av.w, bv.w, acc[3][3]);
        }
        __syncthreads();
    }

#pragma unroll
    for (int i = 0; i < 4; ++i) {
        int o = ty * 4 + i;
        float sc = gamma[o] * rsqrtf(var[o] + 1e-5f);
        float sh = beta[o] - mean[o] * sc;
        float4 v;
        v.x = fmaxf(fmaf(acc[i][0], sc, sh), 0.f);
        v.y = fmaxf(fmaf(acc[i][1], sc, sh), 0.f);
        v.z = fmaxf(fmaf(acc[i][2], sc, sh), 0.f);
        v.w = fmaxf(fmaf(acc[i][3], sc, sh), 0.f);
        *(float4*)(g_w1 + (size_t)(b * CR + o) * HW + px0 + tx * 4) = v;
    }
}

// ---------------------------------------------------------------------------
// K2: w2 = conv2_1x1(w1) + bias. Tile 64o x 64px, 128 thr, 8x4. (round-8)
// Epilogue converts to fp16 (halves store traffic; K3 reads fp16).
// ---------------------------------------------------------------------------
__global__ __launch_bounds__(128) void k2_conv2(
        const float* __restrict__ w2w,
        const float* __restrict__ w2b) {
    __shared__ float As[64 * 68];
    __shared__ float Bs[64 * 64];

    const int tid = threadIdx.x;
    const int tx = tid & 15;
    const int ty = tid >> 4;
    const int px0 = blockIdx.x * 64;
    const int o0 = blockIdx.y * 64;
    const int b = blockIdx.z;

    {
        int k = tid & 63;
        int oh = tid >> 6;
#pragma unroll
        for (int r = 0; r < 32; ++r) {
            int o = 2 * r + oh;
            As[k * 68 + o] = (o0 + o < M2) ? w2w[(o0 + o) * CR + k] : 0.f;
        }
    }
    {
        int j = tid & 63;
        int kh = tid >> 6;
#pragma unroll
        for (int r = 0; r < 32; ++r) {
            int k = 2 * r + kh;
            Bs[k * 64 + j] = g_w1[(size_t)(b * CR + k) * HW + px0 + j];
        }
    }
    __syncthreads();

    float acc[8][4];
#pragma unroll
    for (int i = 0; i < 8; ++i)
#pragma unroll
        for (int u = 0; u < 4; ++u) acc[i][u] = 0.f;

#pragma unroll 8
    for (int k = 0; k < 64; ++k) {
        float4 a0 = *(const float4*)&As[k * 68 + ty * 8];
        float4 a1 = *(const float4*)&As[k * 68 + ty * 8 + 4];
        float4 bv = *(const float4*)&Bs[k * 64 + tx * 4];
        float av[8] = {a0.x, a0.y, a0.z, a0.w, a1.x, a1.y, a1.z, a1.w};
#pragma unroll
        for (int i = 0; i < 8; ++i) {
            acc[i][0] = fmaf(av[i], bv.x, acc[i][0]);
            acc[i][1] = fmaf(av[i], bv.y, acc[i][1]);
            acc[i][2] = fmaf(av[i], bv.z, acc[i][2]);
            acc[i][3] = fmaf(av[i], bv.w, acc[i][3]);
        }
    }

#pragma unroll
    for (int i = 0; i < 8; ++i) {
        int o = o0 + ty * 8 + i;
        if (o >= M2) continue;
        float bias = w2b[o];
        __half2 h0 = __floats2half2_rn(acc[i][0] + bias, acc[i][1] + bias);
        __half2 h1 = __floats2half2_rn(acc[i][2] + bias, acc[i][3] + bias);
        uint2 st;
        st.x = *reinterpret_cast<uint32_t*>(&h0);
        st.y = *reinterpret_cast<uint32_t*>(&h1);
        *(uint2*)(g_w2h + (size_t)(b * M2 + o) * HW + px0 + tx * 4) = st;
    }
}

// ---------------------------------------------------------------------------
// K3: involution reduce. Block = (4-row band, group, batch); 224 threads.
// Thread = 4 px x 4 ch, register double-buffered fp16 weight prefetch.
// Weight loads are 8B (LDG.64) instead of 16B; reg pressure halves -> occ 4.
// ---------------------------------------------------------------------------
__global__ __launch_bounds__(224, 4) void k3_involution(
        const float* __restrict__ x,
        float* __restrict__ out) {
    __shared__ float xs[GC * 10 * 64];

    const int tid = threadIdx.x;
    const int h0 = blockIdx.x * 4;
    const int g = blockIdx.y;
    const int b = blockIdx.z;

    const float* xg = x + (size_t)(b * CC + g * GC) * HW;
    for (int i = tid; i < GC * 10 * 64; i += 224) {
        int ch = i / 640;
        int rem = i - ch * 640;
        int rr = rem >> 6;
        int c = rem & 63;
        int hh = h0 - 3 + rr;
        int ww = c - 3;
        float v = 0.f;
        if (hh >= 0 && hh < HH && ww >= 0 && ww < WW)
            v = xg[(size_t)ch * HW + hh * WW + ww];
        xs[i] = v;
    }
    __syncthreads();

    const int q = tid % 14;
    const int cg = (tid / 14) & 3;
    const int r = tid / 56;
    const int w0 = q * 4;
    const int h = h0 + r;

    const __half* wg = g_w2h + ((size_t)(b * GG + g) * K2T) * HW + h * WW + w0;

    float acc[4][4];
#pragma unroll
    for (int c = 0; c < 4; ++c)
#pragma unroll
        for (int p = 0; p < 4; ++p) acc[c][p] = 0.f;

    // prime: taps of ki = 0 (each uint2 = 4 px of one tap, fp16)
    uint2 wcur[7], wnxt[7];
#pragma unroll
    for (int kj = 0; kj < KK; ++kj)
        wcur[kj] = *(const uint2*)(wg + (size_t)kj * HW);

#pragma unroll
    for (int ki = 0; ki < KK; ++ki) {
        if (ki < KK - 1) {
#pragma unroll
            for (int kj = 0; kj < KK; ++kj)
                wnxt[kj] = *(const uint2*)(wg + (size_t)((ki + 1) * KK + kj) * HW);
        }
        // convert current tap row to fp32
        float4 wv[7];
#pragma unroll
        for (int kj = 0; kj < KK; ++kj) {
            __half2 p0 = *reinterpret_cast<const __half2*>(&wcur[kj].x);
            __half2 p1 = *reinterpret_cast<const __half2*>(&wcur[kj].y);
            float2 f0 = __half22float2(p0);
            float2 f1 = __half22float2(p1);
            wv[kj] = make_float4(f0.x, f0.y, f1.x, f1.y);
        }
#pragma unroll
        for (int c = 0; c < 4; ++c) {
            const float* xr = &xs[(cg * 4 + c) * 640 + (r + ki) * 64 + w0];
            float4 xa = *(const float4*)(xr);
            float4 xb = *(const float4*)(xr + 4);
            float4 xc = *(const float4*)(xr + 8);
            float xw[12] = {xa.x, xa.y, xa.z, xa.w,
                            xb.x, xb.y, xb.z, xb.w,
                            xc.x, xc.y, xc.z, xc.w};
#pragma unroll
            for (int kj = 0; kj < KK; ++kj) {
                acc[c][0] = fmaf(wv[kj].x, xw[kj + 0], acc[c][0]);
                acc[c][1] = fmaf(wv[kj].y, xw[kj + 1], acc[c][1]);
                acc[c][2] = fmaf(wv[kj].z, xw[kj + 2], acc[c][2]);
                acc[c][3] = fmaf(wv[kj].w, xw[kj + 3], acc[c][3]);
            }
        }
#pragma unroll
        for (int kj = 0; kj < KK; ++kj)
            wcur[kj] = wnxt[kj];
    }

#pragma unroll
    for (int c = 0; c < 4; ++c) {
        float4 v = make_float4(acc[c][0], acc[c][1], acc[c][2], acc[c][3]);
        *(float4*)(out + (size_t)(b * CC + g * GC + cg * 4 + c) * HW
                   + h * WW + w0) = v;
    }
}

// ---------------------------------------------------------------------------
extern "C" void kernel_launch(void* const* d_in, const int* in_sizes, int n_in,
                              void* d_out, int out_size) {
    const float* x     = (const float*)d_in[0];
    const float* w1w   = (const float*)d_in[1];
    const float* gamma = (const float*)d_in[2];
    const float* beta  = (const float*)d_in[3];
    const float* mean  = (const float*)d_in[4];
    const float* var   = (const float*)d_in[5];
    const float* w2w   = (const float*)d_in[6];
    const float* w2b   = (const float*)d_in[7];
    float* out = (float*)d_out;

    dim3 g1(HW / 32, BB);                       // 98 x 4 = 392
    k1_conv1_bn_relu<<<g1, 128>>>(x, w1w, gamma, beta, mean, var);

    dim3 g2(HW / 64, (M2 + 63) / 64, BB);       // 49 x 13 x 4 = 2548
    k2_conv2<<<g2, 128>>>(w2w, w2b);

    dim3 g3(HH / 4, GG, BB);                    // 14 x 16 x 4 = 896
    k3_involution<<<g3, 224>>>(x, out);
}